// round 8
// baseline (speedup 1.0000x reference)
#include <cuda_runtime.h>
#include <cstdint>

// RollerPooling forward — persistent grid, 2 rows per warp per iteration,
// software-prefetched double buffer (next iteration's loads issued before
// current iteration's compute), zero shared memory.
// out[e][j] = (csum[min(j+w,128)] - csum[j]) / w,  w = 129 - target_size[e].
// Per row: warp shuffle scan -> shuffle gather (w warp-uniform: index
// 4*lane+k+w lives in register c_{(k+b)&3} of lane lane+q+carry, w=4q+b).

#define N_CH 128
#define WARPS_PER_BLOCK 8
#define THREADS (WARPS_PER_BLOCK * 32)
#define NUM_SMS 152
#define CTAS_PER_SM 6
#define GRID_BLOCKS (NUM_SMS * CTAS_PER_SM)

__device__ __forceinline__ float4 roller_row(float4 v, int w, int lane) {
    const unsigned m = 0xffffffffu;

    // Lane sum + inclusive warp scan of lane sums.
    float s = v.x + v.y + v.z + v.w;
    float inc = s;
    #pragma unroll
    for (int o = 1; o < 32; o <<= 1) {
        float t = __shfl_up_sync(m, inc, o);
        if (lane >= o) inc += t;
    }
    const float excl = inc - s;

    // Exclusive csum at this lane's 4 elements (registers only).
    const float c0 = excl;
    const float c1 = c0 + v.x;
    const float c2 = c1 + v.y;
    const float c3 = c2 + v.z;

    const float total = __shfl_sync(m, inc, 31);   // csum[128]

    const int q = w >> 2;
    const int b = w & 3;
    const float invw = 1.0f / (float)w;

    // Gather csum[4*lane + k + w] via shuffles (srcLane = (4*lane+k+w)>>2;
    // mod-32 wrap for OOB lanes is overridden by the clamp below).
    const float g0 = __shfl_sync(m, c0, lane + q + (0 < b ? 1 : 0));
    const float g1 = __shfl_sync(m, c1, lane + q + (1 < b ? 1 : 0));
    const float g2 = __shfl_sync(m, c2, lane + q + (2 < b ? 1 : 0));
    const float g3 = __shfl_sync(m, c3, lane + q + (3 < b ? 1 : 0));

    // Permute: end-of-window csum for output k uses residue (k+b)&3.
    float e0, e1, e2, e3;
    switch (b) {   // warp-uniform branch
        case 0:  e0 = g0; e1 = g1; e2 = g2; e3 = g3; break;
        case 1:  e0 = g1; e1 = g2; e2 = g3; e3 = g0; break;
        case 2:  e0 = g2; e1 = g3; e2 = g0; e3 = g1; break;
        default: e0 = g3; e1 = g0; e2 = g1; e3 = g2; break;
    }

    // Clamp: window ends past 128 read csum[128] = total.
    const int j = lane << 2;
    if (j + 0 + w >= N_CH) e0 = total;
    if (j + 1 + w >= N_CH) e1 = total;
    if (j + 2 + w >= N_CH) e2 = total;
    if (j + 3 + w >= N_CH) e3 = total;

    float4 o4;
    o4.x = (e0 - c0) * invw;
    o4.y = (e1 - c1) * invw;
    o4.z = (e2 - c2) * invw;
    o4.w = (e3 - c3) * invw;
    return o4;
}

__global__ __launch_bounds__(THREADS, CTAS_PER_SM)
void roller_pooling_kernel(const float* __restrict__ hidden,
                           const int* __restrict__ target_size,
                           float* __restrict__ out,
                           int n_edges) {
    const int warp = threadIdx.x >> 5;
    const int lane = threadIdx.x & 31;
    const int gwarp = blockIdx.x * WARPS_PER_BLOCK + warp;   // global warp id
    const int nwarps = GRID_BLOCKS * WARPS_PER_BLOCK;        // total warps
    const int npairs = (n_edges + 1) >> 1;                   // row pairs

    int p = gwarp;
    if (p >= npairs) return;

    // Prologue: load pair p.
    float4 vA, vB;
    int tsA, tsB;
    {
        const int eA = p * 2, eB = eA + 1;
        vA = reinterpret_cast<const float4*>(hidden + (size_t)eA * N_CH)[lane];
        vB = (eB < n_edges)
               ? reinterpret_cast<const float4*>(hidden + (size_t)eB * N_CH)[lane]
               : make_float4(0.f, 0.f, 0.f, 0.f);
        tsA = target_size[eA];
        tsB = (eB < n_edges) ? target_size[eB] : 1;
    }

    while (true) {
        const int pn = p + nwarps;

        // Prefetch next pair's loads BEFORE this pair's serial compute —
        // the memory pipe stays busy through the shuffle chains.
        float4 nvA, nvB;
        int ntsA = 1, ntsB = 1;
        const bool more = pn < npairs;
        if (more) {
            const int eA = pn * 2, eB = eA + 1;
            nvA = reinterpret_cast<const float4*>(hidden + (size_t)eA * N_CH)[lane];
            nvB = (eB < n_edges)
                    ? reinterpret_cast<const float4*>(hidden + (size_t)eB * N_CH)[lane]
                    : make_float4(0.f, 0.f, 0.f, 0.f);
            ntsA = target_size[eA];
            ntsB = (eB < n_edges) ? target_size[eB] : 1;
        }

        // Compute + store pair p.
        {
            const int eA = p * 2, eB = eA + 1;
            float4 oA = roller_row(vA, (N_CH + 1) - tsA, lane);
            reinterpret_cast<float4*>(out + (size_t)eA * N_CH)[lane] = oA;
            if (eB < n_edges) {
                float4 oB = roller_row(vB, (N_CH + 1) - tsB, lane);
                reinterpret_cast<float4*>(out + (size_t)eB * N_CH)[lane] = oB;
            }
        }

        if (!more) break;
        vA = nvA; vB = nvB; tsA = ntsA; tsB = ntsB;
        p = pn;
    }
}

extern "C" void kernel_launch(void* const* d_in, const int* in_sizes, int n_in,
                              void* d_out, int out_size) {
    const float* hidden = (const float*)d_in[0];
    const int* target_size = (const int*)d_in[1];
    float* out = (float*)d_out;
    const int n_edges = in_sizes[1];

    roller_pooling_kernel<<<GRID_BLOCKS, THREADS>>>(hidden, target_size, out, n_edges);
}

// round 9
// speedup vs baseline: 1.1746x; 1.1746x over previous
#include <cuda_runtime.h>
#include <cstdint>

// RollerPooling forward — 2 rows per warp with INTERLEAVED compute chains
// (both rows advance together through every scan/gather step: 2-way ILP in
// the serial SHFL-latency chain). Zero shared memory.
// out[e][j] = (csum[min(j+w,128)] - csum[j]) / w,  w = 129 - target_size[e].
// Gather uses warp-uniform w: index 4*lane+k+w lives in register c_{(k+b)&3}
// of lane lane+q+carry, where w=4q+b.

#define N_CH 128
#define WARPS_PER_BLOCK 8
#define THREADS (WARPS_PER_BLOCK * 32)
#define CTAS_PER_SM 6

__global__ __launch_bounds__(THREADS, CTAS_PER_SM)
void roller_pooling_kernel(const float* __restrict__ hidden,
                           const int* __restrict__ target_size,
                           float* __restrict__ out,
                           int n_edges) {
    const int warp = threadIdx.x >> 5;
    const int lane = threadIdx.x & 31;
    const int e0 = (blockIdx.x * WARPS_PER_BLOCK + warp) * 2;
    if (e0 >= n_edges) return;

    const bool hasB = (e0 + 1) < n_edges;
    const unsigned m = 0xffffffffu;

    // Front-batched global loads (2x LDG.128 + 2x LDG.32 in flight).
    float4 v[2];
    v[0] = reinterpret_cast<const float4*>(hidden + (size_t)e0 * N_CH)[lane];
    v[1] = hasB
         ? reinterpret_cast<const float4*>(hidden + (size_t)(e0 + 1) * N_CH)[lane]
         : make_float4(0.f, 0.f, 0.f, 0.f);
    int ts[2];
    ts[0] = target_size[e0];
    ts[1] = hasB ? target_size[e0 + 1] : 1;

    // ---- Both rows advance together through every stage ----

    // Lane sums.
    float s[2], inc[2];
    #pragma unroll
    for (int r = 0; r < 2; r++) {
        s[r] = v[r].x + v[r].y + v[r].z + v[r].w;
        inc[r] = s[r];
    }

    // Interleaved inclusive warp scans (two independent SHFL chains pipeline).
    #pragma unroll
    for (int o = 1; o < 32; o <<= 1) {
        float t0 = __shfl_up_sync(m, inc[0], o);
        float t1 = __shfl_up_sync(m, inc[1], o);
        if (lane >= o) { inc[0] += t0; inc[1] += t1; }
    }

    // Exclusive csum at this lane's 4 elements (registers only).
    float c0[2], c1[2], c2[2], c3[2], total[2];
    #pragma unroll
    for (int r = 0; r < 2; r++) {
        c0[r] = inc[r] - s[r];
        c1[r] = c0[r] + v[r].x;
        c2[r] = c1[r] + v[r].y;
        c3[r] = c2[r] + v[r].z;
    }
    total[0] = __shfl_sync(m, inc[0], 31);
    total[1] = __shfl_sync(m, inc[1], 31);

    int w[2], q[2], b[2];
    float invw[2];
    #pragma unroll
    for (int r = 0; r < 2; r++) {
        w[r] = (N_CH + 1) - ts[r];
        q[r] = w[r] >> 2;
        b[r] = w[r] & 3;
        invw[r] = 1.0f / (float)w[r];
    }

    // Interleaved gathers: csum[4*lane + k + w] via shuffles
    // (srcLane = (4*lane+k+w)>>2; mod-32 wrap overridden by clamp below).
    float g0[2], g1[2], g2[2], g3[2];
    #pragma unroll
    for (int r = 0; r < 2; r++) {
        g0[r] = __shfl_sync(m, c0[r], lane + q[r] + (0 < b[r] ? 1 : 0));
        g1[r] = __shfl_sync(m, c1[r], lane + q[r] + (1 < b[r] ? 1 : 0));
        g2[r] = __shfl_sync(m, c2[r], lane + q[r] + (2 < b[r] ? 1 : 0));
        g3[r] = __shfl_sync(m, c3[r], lane + q[r] + (3 < b[r] ? 1 : 0));
    }

    const int j = lane << 2;
    float4 o4[2];
    #pragma unroll
    for (int r = 0; r < 2; r++) {
        // Permute: end-of-window csum for output k uses residue (k+b)&3.
        float e0v, e1v, e2v, e3v;
        switch (b[r]) {   // warp-uniform branch
            case 0:  e0v = g0[r]; e1v = g1[r]; e2v = g2[r]; e3v = g3[r]; break;
            case 1:  e0v = g1[r]; e1v = g2[r]; e2v = g3[r]; e3v = g0[r]; break;
            case 2:  e0v = g2[r]; e1v = g3[r]; e2v = g0[r]; e3v = g1[r]; break;
            default: e0v = g3[r]; e1v = g0[r]; e2v = g1[r]; e3v = g2[r]; break;
        }
        // Clamp: window ends past 128 read csum[128] = total.
        if (j + 0 + w[r] >= N_CH) e0v = total[r];
        if (j + 1 + w[r] >= N_CH) e1v = total[r];
        if (j + 2 + w[r] >= N_CH) e2v = total[r];
        if (j + 3 + w[r] >= N_CH) e3v = total[r];

        o4[r].x = (e0v - c0[r]) * invw[r];
        o4[r].y = (e1v - c1[r]) * invw[r];
        o4[r].z = (e2v - c2[r]) * invw[r];
        o4[r].w = (e3v - c3[r]) * invw[r];
    }

    // Batched stores back-to-back.
    reinterpret_cast<float4*>(out + (size_t)e0 * N_CH)[lane] = o4[0];
    if (hasB)
        reinterpret_cast<float4*>(out + (size_t)(e0 + 1) * N_CH)[lane] = o4[1];
}

extern "C" void kernel_launch(void* const* d_in, const int* in_sizes, int n_in,
                              void* d_out, int out_size) {
    const float* hidden = (const float*)d_in[0];
    const int* target_size = (const int*)d_in[1];
    float* out = (float*)d_out;
    const int n_edges = in_sizes[1];

    const int rows_per_block = WARPS_PER_BLOCK * 2;
    const int blocks = (n_edges + rows_per_block - 1) / rows_per_block;
    roller_pooling_kernel<<<blocks, THREADS>>>(hidden, target_size, out, n_edges);
}

// round 10
// speedup vs baseline: 1.2166x; 1.0358x over previous
#include <cuda_runtime.h>
#include <cstdint>

// RollerPooling forward — champion config: 16 warps/block, 2 rows per warp,
// regs 32 / occ ~82%, streaming cache ops, zero shared memory, branch-free
// row-B handling (clamped index double-write is value-identical).
// out[e][j] = (csum[min(j+w,128)] - csum[j]) / w,  w = 129 - target_size[e].
// Per row: warp shuffle scan -> shuffle gather (w warp-uniform: index
// 4*lane+k+w lives in register c_{(k+b)&3} of lane lane+q+carry, w=4q+b).

#define N_CH 128
#define WARPS_PER_BLOCK 16
#define THREADS (WARPS_PER_BLOCK * 32)

__device__ __forceinline__ float4 roller_row(float4 v, int w, int lane) {
    const unsigned m = 0xffffffffu;

    // Lane sum + inclusive warp scan of lane sums.
    float s = v.x + v.y + v.z + v.w;
    float inc = s;
    #pragma unroll
    for (int o = 1; o < 32; o <<= 1) {
        float t = __shfl_up_sync(m, inc, o);
        if (lane >= o) inc += t;
    }
    const float excl = inc - s;

    // Exclusive csum at this lane's 4 elements (registers only).
    const float c0 = excl;
    const float c1 = c0 + v.x;
    const float c2 = c1 + v.y;
    const float c3 = c2 + v.z;

    const float total = __shfl_sync(m, inc, 31);   // csum[128]

    const int q = w >> 2;
    const int b = w & 3;
    const float invw = 1.0f / (float)w;

    // Gather csum[4*lane + k + w] via shuffles (srcLane = (4*lane+k+w)>>2;
    // mod-32 wrap for OOB lanes is overridden by the clamp below).
    const float g0 = __shfl_sync(m, c0, lane + q + (0 < b ? 1 : 0));
    const float g1 = __shfl_sync(m, c1, lane + q + (1 < b ? 1 : 0));
    const float g2 = __shfl_sync(m, c2, lane + q + (2 < b ? 1 : 0));
    const float g3 = __shfl_sync(m, c3, lane + q + (3 < b ? 1 : 0));

    // Permute: end-of-window csum for output k uses residue (k+b)&3.
    float e0, e1, e2, e3;
    switch (b) {   // warp-uniform branch
        case 0:  e0 = g0; e1 = g1; e2 = g2; e3 = g3; break;
        case 1:  e0 = g1; e1 = g2; e2 = g3; e3 = g0; break;
        case 2:  e0 = g2; e1 = g3; e2 = g0; e3 = g1; break;
        default: e0 = g3; e1 = g0; e2 = g1; e3 = g2; break;
    }

    // Clamp: window ends past 128 read csum[128] = total.
    const int j = lane << 2;
    if (j + 0 + w >= N_CH) e0 = total;
    if (j + 1 + w >= N_CH) e1 = total;
    if (j + 2 + w >= N_CH) e2 = total;
    if (j + 3 + w >= N_CH) e3 = total;

    float4 o4;
    o4.x = (e0 - c0) * invw;
    o4.y = (e1 - c1) * invw;
    o4.z = (e2 - c2) * invw;
    o4.w = (e3 - c3) * invw;
    return o4;
}

__global__ __launch_bounds__(THREADS)
void roller_pooling_kernel(const float* __restrict__ hidden,
                           const int* __restrict__ target_size,
                           float* __restrict__ out,
                           int n_edges) {
    const int warp = threadIdx.x >> 5;
    const int lane = threadIdx.x & 31;
    const int eA = (blockIdx.x * WARPS_PER_BLOCK + warp) * 2;
    if (eA >= n_edges) return;

    // Branch-free second row: clamp to last valid row. If clamped, row B
    // recomputes row A from identical inputs -> identical double-write.
    const int eB = min(eA + 1, n_edges - 1);

    // Front-batched streaming loads (2x LDG.128 + 2x LDG.32 in flight).
    float4 vA = __ldcs(reinterpret_cast<const float4*>(hidden + (size_t)eA * N_CH) + lane);
    float4 vB = __ldcs(reinterpret_cast<const float4*>(hidden + (size_t)eB * N_CH) + lane);
    const int tsA = __ldcs(target_size + eA);
    const int tsB = __ldcs(target_size + eB);

    float4 oA = roller_row(vA, (N_CH + 1) - tsA, lane);
    __stcs(reinterpret_cast<float4*>(out + (size_t)eA * N_CH) + lane, oA);

    float4 oB = roller_row(vB, (N_CH + 1) - tsB, lane);
    __stcs(reinterpret_cast<float4*>(out + (size_t)eB * N_CH) + lane, oB);
}

extern "C" void kernel_launch(void* const* d_in, const int* in_sizes, int n_in,
                              void* d_out, int out_size) {
    const float* hidden = (const float*)d_in[0];
    const int* target_size = (const int*)d_in[1];
    float* out = (float*)d_out;
    const int n_edges = in_sizes[1];

    const int rows_per_block = WARPS_PER_BLOCK * 2;
    const int blocks = (n_edges + rows_per_block - 1) / rows_per_block;
    roller_pooling_kernel<<<blocks, THREADS>>>(hidden, target_size, out, n_edges);
}